// round 12
// baseline (speedup 1.0000x reference)
#include <cuda_runtime.h>
#include <math.h>
#include <cstdint>

#define BB   4
#define RR   64
#define CC   192
#define WNN  16
#define WSZ  16
#define TAPS 9

// ---------------- device scratch ----------------
__device__ float g_t[BB * WNN];
__device__ float g_WeffB[BB * TAPS * 6 * 6144];        // B in chunked frag order
__device__ float g_xA[(size_t)BB * 3 * RR * 6 * 2048]; // A frag-order, 3 dx shifts
__device__ float g_k1T[TAPS * WNN * CC];               // k1 transposed [tap][s][c]

__device__ __forceinline__ uint32_t f2tf(float f) {
    uint32_t u; asm("cvt.rna.tf32.f32 %0, %1;" : "=r"(u) : "f"(f)); return u;
}
__device__ __forceinline__ uint32_t smem_u32(const void* p) {
    uint32_t a;
    asm("{ .reg .u64 t; cvta.to.shared.u64 t, %1; cvt.u32.u64 %0, t; }"
        : "=r"(a) : "l"(p));
    return a;
}
__device__ __forceinline__ void mma_tf32(float* d, const uint32_t* a, const uint32_t* b) {
    asm volatile(
        "mma.sync.aligned.m16n8k8.row.col.f32.tf32.tf32.f32 "
        "{%0,%1,%2,%3}, {%4,%5,%6,%7}, {%8,%9}, {%0,%1,%2,%3};"
        : "+f"(d[0]), "+f"(d[1]), "+f"(d[2]), "+f"(d[3])
        : "r"(a[0]), "r"(a[1]), "r"(a[2]), "r"(a[3]), "r"(b[0]), "r"(b[1]));
}
#define CP_ASYNC16(dst, src) \
    asm volatile("cp.async.ca.shared.global [%0], [%1], 16;" :: "r"(dst), "l"(src))
#define CP_COMMIT() asm volatile("cp.async.commit_group;" ::: "memory")
#define CP_WAIT(n)  asm volatile("cp.async.wait_group %0;" :: "n"(n) : "memory")

// ---------------------------------------------------------------------------
// Kernel X: build A operand in mma-fragment order, tf32-rounded (validated)
// ---------------------------------------------------------------------------
__global__ void __launch_bounds__(256)
kX(const float* __restrict__ x) {
    int sy  = blockIdx.x;
    int dxi = blockIdx.y;
    int b   = blockIdx.z;
    int wid  = threadIdx.x >> 5;
    int lane = threadIdx.x & 31;

    int px = lane >> 1;
    int kk = (lane & 1) * 4;

    const float* xr = x + ((size_t)(b * RR + sy) * RR) * CC;

#pragma unroll 1
    for (int u = wid; u < 96; u += 8) {
        int cg = u >> 4;
        int ks = (u >> 2) & 3;
        int mi = u & 3;
        int sx = mi * 16 + px + dxi - 1;

        float4 v = make_float4(0.f, 0.f, 0.f, 0.f);
        if ((unsigned)sx < RR)
            v = *(const float4*)(xr + (size_t)sx * CC + cg * 32 + ks * 8 + kk);

        float* dst = g_xA + ((((size_t)b * 3 + dxi) * RR + sy) * 6 + cg) * 2048
                         + (ks * 4 + mi) * 128;
        int rbase = (kk >> 2) * 2 + (px >> 3);
        uint32_t vv[4] = { f2tf(v.x), f2tf(v.y), f2tf(v.z), f2tf(v.w) };
#pragma unroll
        for (int i = 0; i < 4; i++)
            dst[((px & 7) * 4 + i) * 4 + rbase] = __uint_as_float(vv[i]);
    }
}

// ---------------------------------------------------------------------------
// Kernel T: transpose conv1_w for coalesced kW reads (validated)
// ---------------------------------------------------------------------------
__global__ void kT(const float* __restrict__ k1) {
    int i = blockIdx.x * 256 + threadIdx.x;
    if (i >= TAPS * WNN * CC) return;
    int tap = i / (WNN * CC);
    int rc  = i - tap * (WNN * CC);
    g_k1T[i] = k1[(size_t)rc * TAPS + tap];
}

// ---------------------------------------------------------------------------
// Kernel A: pooled depthwise stats -> downchannel logits (validated)
// ---------------------------------------------------------------------------
__global__ void kA(const float* __restrict__ x, const float* __restrict__ k1,
                   const float* __restrict__ dcw, const float* __restrict__ dcb) {
    int b   = blockIdx.x >> 4;
    int win = blockIdx.x & 15;
    int c   = threadIdx.x;
    int rb  = win >> 2, cb = win & 3;
    const float* xp = x + ((size_t)b * RR * RR) * CC + c;
    int base = (rb * WSZ) * RR + cb * WSZ;

    float T = 0.f, r0 = 0.f, r15 = 0.f, c0 = 0.f, c15 = 0.f;
    float e00 = 0.f, e0f = 0.f, ef0 = 0.f, eff = 0.f;
    for (int i = 0; i < 16; i++) {
        float rowacc = 0.f, vj0 = 0.f, vj15 = 0.f;
#pragma unroll
        for (int j = 0; j < 16; j++) {
            float v = xp[(size_t)(base + i * RR + j) * CC];
            rowacc += v;
            if (j == 0)  { c0  += v; vj0  = v; }
            if (j == 15) { c15 += v; vj15 = v; }
        }
        T += rowacc;
        if (i == 0)  { r0  = rowacc; e00 = vj0; e0f = vj15; }
        if (i == 15) { r15 = rowacc; ef0 = vj0; eff = vj15; }
    }

    float Rex[3] = { r15, 0.f, r0 };
    float Cex[3] = { c15, 0.f, c0 };
    const float* kp = k1 + (size_t)(win * CC + c) * TAPS;
    float pooled = 0.f;
#pragma unroll
    for (int p = 0; p < 3; p++) {
#pragma unroll
        for (int q = 0; q < 3; q++) {
            float corner = 0.f;
            if (p == 0 && q == 0) corner = eff;
            if (p == 0 && q == 2) corner = ef0;
            if (p == 2 && q == 0) corner = e0f;
            if (p == 2 && q == 2) corner = e00;
            float S = T - Rex[p] - Cex[q] + corner;
            pooled += kp[p * 3 + q] * S;
        }
    }
    pooled *= (1.f / 256.f);
    float contrib = pooled * dcw[win * CC + c];

    __shared__ float red[192];
    red[c] = contrib;
    __syncthreads();
    for (int s = 96; s >= 6; s >>= 1) {
        if (c < s) red[c] += red[c + s];
        __syncthreads();
    }
    if (c == 0) {
        float tot = red[0] + red[1] + red[2] + red[3] + red[4] + red[5];
        g_t[b * WNN + win] = tot + dcb[win];
    }
}

// ---------------------------------------------------------------------------
// Kernel W: fused MLP + Weff. NEW B word order (per b,tap,cg chunk of 6144):
//   word = (n8*2 + (ks>>1))*128 + frag_lane*4 + (ks&1)*2 + j
// where n8 = n>>3, frag_lane = (n&7)*4 + (k32&3), ks = k32>>3, j = (k32>>2)&1
// so compute-side reads are LDS.128 covering 2 consecutive ks.
// ---------------------------------------------------------------------------
__global__ void __launch_bounds__(192)
kW(const float* __restrict__ gkb, const float* __restrict__ fw,
   const float* __restrict__ l1w, const float* __restrict__ l1b,
   const float* __restrict__ l2w, const float* __restrict__ l2b,
   const float* __restrict__ gkw) {
    int n = blockIdx.x;          // cout
    int c = threadIdx.x;         // cin = k
    __shared__ float ts[64], hs[256];
    __shared__ float sw_[64], swg[64];

    if (c < 64) ts[c] = g_t[c];
    __syncthreads();
    for (int u = c; u < 256; u += 192) {
        int b = u >> 6, j = u & 63;
        float a = l1b[j];
#pragma unroll
        for (int s = 0; s < 16; s++) a += ts[b * 16 + s] * l1w[j * 16 + s];
        hs[u] = 0.5f * a * (1.f + erff(a * 0.70710678118654752f));
    }
    __syncthreads();
    if (c < 64) {
        int b = c >> 4, s = c & 15;
        float a = l2b[s];
#pragma unroll
        for (int j = 0; j < 64; j++) a += hs[b * 64 + j] * l2w[s * 64 + j];
        float wv = 1.f / (1.f + expf(-a));
        sw_[c] = wv;
        swg[c] = wv * gkw[s];
    }
    __syncthreads();

    float f[17];
    const float* fp = fw + (size_t)n * ((WNN + 1) * CC) + c;
#pragma unroll
    for (int s = 0; s < 17; s++) f[s] = fp[s * CC];
    float g0 = gkb[0];

    int cg  = c >> 5, k32 = c & 31;
    int ks  = k32 >> 3, j = (k32 >> 2) & 1;
    int fl  = (n & 7) * 4 + (k32 & 3);
    int wrd = ((n >> 3) * 2 + (ks >> 1)) * 128 + fl * 4 + (ks & 1) * 2 + j;

#pragma unroll 1
    for (int tap = 0; tap < 9; tap++) {
        float kv[16];
        const float* kt = g_k1T + (size_t)tap * WNN * CC + c;
#pragma unroll
        for (int s = 0; s < 16; s++) kv[s] = kt[s * CC];
#pragma unroll
        for (int b = 0; b < 4; b++) {
            float acc = 0.f, ga = g0;
#pragma unroll
            for (int s = 0; s < 16; s++) {
                acc = fmaf(sw_[b * 16 + s] * kv[s], f[s], acc);
                ga  = fmaf(swg[b * 16 + s], kv[s], ga);
            }
            acc = fmaf(ga, f[16], acc);
            g_WeffB[((size_t)(b * 9 + tap) * 6 + cg) * 6144 + wrd] =
                __uint_as_float(f2tf(acc));
        }
    }
}

// ---------------------------------------------------------------------------
// Kernel D: tf32 mma.sync implicit GEMM.
// CTA: M=64 x N=192, 8 warps (2m x 4n), warp = 32m x 48n, acc 48/thread.
// B: cp.async -> smem, 3 stages, 1 barrier/chunk (twin m-warps share via smem).
// A: direct LDG.128 from fragment-ordered gmem (n-warps dedup in L1).
// ~115 regs -> occupancy 2 -> 16 warps/SM.
// ---------------------------------------------------------------------------
#define BSTG 6144

__global__ void __launch_bounds__(256, 2)
kD(const float* __restrict__ fb, float* __restrict__ out) {
    __shared__ float smB[3][BSTG];

    int tid  = threadIdx.x;
    int lane = tid & 31;
    int wid  = tid >> 5;
    int b    = blockIdx.y;
    int row  = blockIdx.x;             // image row

    const float* WB = g_WeffB + (size_t)b * TAPS * 6 * 6144;
    int wm = wid >> 2;                 // m half (0/1)
    int wq = wid & 3;                  // n quarter

    float acc[2][6][4];
#pragma unroll
    for (int mi = 0; mi < 2; mi++)
#pragma unroll
        for (int ni = 0; ni < 6; ni++)
#pragma unroll
            for (int r = 0; r < 4; r++) acc[mi][ni][r] = 0.f;

    auto stageB = [&](int kc, int slot) {
        int tap = kc / 6, cg = kc - tap * 6;
        const float* src = WB + ((size_t)tap * 6 + cg) * 6144;
        uint32_t d0 = smem_u32(&smB[slot][0]);
#pragma unroll
        for (int j = 0; j < 6; j++) {
            int i4 = tid + 256 * j;
            CP_ASYNC16(d0 + i4 * 16, src + i4 * 4);
        }
    };
    auto computeChunk = [&](int kc, int slot) {
        int tap = kc / 6, cg = kc - tap * 6;
        int dy = tap / 3 - 1, dxi = tap % 3;
        int sy = row + dy;
        if ((unsigned)sy >= RR) return;          // zero A -> no contribution
        const float* base = g_xA +
            ((((size_t)b * 3 + dxi) * RR + sy) * 6 + cg) * 2048;
        const float* bs = smB[slot];
#pragma unroll
        for (int ks2 = 0; ks2 < 2; ks2++) {
            // B frags for 2 consecutive ks: LDS.128
            float4 bv[6];
#pragma unroll
            for (int ni = 0; ni < 6; ni++) {
                int n8 = wq * 6 + ni;
                bv[ni] = *(const float4*)(bs + (n8 * 2 + ks2) * 128 + lane * 4);
            }
#pragma unroll
            for (int kss = 0; kss < 2; kss++) {
                int ks = ks2 * 2 + kss;
                uint32_t af[2][4];
#pragma unroll
                for (int mi = 0; mi < 2; mi++) {
                    float4 v = *(const float4*)(base +
                        (ks * 4 + wm * 2 + mi) * 128 + lane * 4);
                    af[mi][0] = __float_as_uint(v.x);
                    af[mi][1] = __float_as_uint(v.y);
                    af[mi][2] = __float_as_uint(v.z);
                    af[mi][3] = __float_as_uint(v.w);
                }
#pragma unroll
                for (int mi = 0; mi < 2; mi++)
#pragma unroll
                    for (int ni = 0; ni < 6; ni++) {
                        uint32_t bb[2];
                        bb[0] = __float_as_uint(kss ? bv[ni].z : bv[ni].x);
                        bb[1] = __float_as_uint(kss ? bv[ni].w : bv[ni].y);
                        mma_tf32(acc[mi][ni], af[mi], bb);
                    }
            }
        }
    };

    // ---- prologue ----
    stageB(0, 0); CP_COMMIT();
    stageB(1, 1); CP_COMMIT();

#pragma unroll 1
    for (int kc = 0; kc < 54; kc++) {
        if (kc < 52) CP_WAIT(1); else CP_WAIT(0);
        __syncthreads();
        if (kc + 2 < 54) { stageB(kc + 2, (kc + 2) % 3); CP_COMMIT(); }
        computeChunk(kc, kc % 3);
    }

    // ---- epilogue: +bias, STG.64 ----
#pragma unroll
    for (int ni = 0; ni < 6; ni++) {
        int co = wq * 48 + ni * 8 + (lane & 3) * 2;
        float bx = fb[co], by = fb[co + 1];
#pragma unroll
        for (int mi = 0; mi < 2; mi++) {
            int m0 = row * 64 + wm * 32 + mi * 16 + (lane >> 2);
            size_t o0 = ((size_t)b * RR * RR + m0) * CC + co;
            *(float2*)(out + o0) =
                make_float2(acc[mi][ni][0] + bx, acc[mi][ni][1] + by);
            *(float2*)(out + o0 + (size_t)8 * CC) =
                make_float2(acc[mi][ni][2] + bx, acc[mi][ni][3] + by);
        }
    }
}

// ---------------------------------------------------------------------------
extern "C" void kernel_launch(void* const* d_in, const int* in_sizes, int n_in,
                              void* d_out, int out_size) {
    const float* x   = (const float*)d_in[0];
    const float* k1  = (const float*)d_in[1];
    const float* dcw = (const float*)d_in[2];
    const float* dcb = (const float*)d_in[3];
    const float* l1w = (const float*)d_in[4];
    const float* l1b = (const float*)d_in[5];
    const float* l2w = (const float*)d_in[6];
    const float* l2b = (const float*)d_in[7];
    const float* gkw = (const float*)d_in[8];
    const float* gkb = (const float*)d_in[9];
    const float* fw  = (const float*)d_in[10];
    const float* fb  = (const float*)d_in[11];
    float* out = (float*)d_out;

    static cudaStream_t s1 = nullptr;
    static cudaEvent_t evF = nullptr, evJ = nullptr;
    if (s1 == nullptr) {
        cudaStreamCreateWithFlags(&s1, cudaStreamNonBlocking);
        cudaEventCreateWithFlags(&evF, cudaEventDisableTiming);
        cudaEventCreateWithFlags(&evJ, cudaEventDisableTiming);
    }

    // fork: side chain (kT -> kA -> kW) runs concurrently with kX
    cudaEventRecord(evF, 0);
    cudaStreamWaitEvent(s1, evF, 0);

    kT<<<(TAPS * WNN * CC + 255) / 256, 256, 0, s1>>>(k1);
    kA<<<BB * WNN, CC, 0, s1>>>(x, k1, dcw, dcb);
    kW<<<CC, CC, 0, s1>>>(gkb, fw, l1w, l1b, l2w, l2b, gkw);
    cudaEventRecord(evJ, s1);

    kX<<<dim3(RR, 3, BB), 256>>>(x);

    // join
    cudaStreamWaitEvent(0, evJ, 0);
    dim3 g(RR, BB);   // 64 row-tiles x 4 batches = 256 CTAs
    kD<<<g, 256>>>(fb, out);
}

// round 13
// speedup vs baseline: 1.7645x; 1.7645x over previous
#include <cuda_runtime.h>
#include <cuda_fp16.h>
#include <math.h>
#include <cstdint>

#define BB   4
#define RR   64
#define CC   192
#define WNN  16
#define WSZ  16
#define TAPS 9

// ---------------- device scratch ----------------
__device__ float  g_t[BB * WNN];
__device__ uint4  g_xAh[(size_t)BB * 3 * RR * 1536];   // A fp16 frag-order (18.9MB)
__device__ __half g_WBh[(size_t)BB * TAPS * 6 * 6144]; // B fp16 frag-order (2.65MB)
__device__ float  g_k1T[TAPS * WNN * CC];              // k1 transposed [tap][s][c]

__device__ __forceinline__ void mma_f16(float* d, const uint32_t* a, const uint32_t* b) {
    asm volatile(
        "mma.sync.aligned.m16n8k16.row.col.f32.f16.f16.f32 "
        "{%0,%1,%2,%3}, {%4,%5,%6,%7}, {%8,%9}, {%0,%1,%2,%3};"
        : "+f"(d[0]), "+f"(d[1]), "+f"(d[2]), "+f"(d[3])
        : "r"(a[0]), "r"(a[1]), "r"(a[2]), "r"(a[3]), "r"(b[0]), "r"(b[1]));
}

// ---------------------------------------------------------------------------
// Kernel X: build fp16 A operand in m16n8k16 fragment order, 3 dx shifts.
// Per (b,dxi,sy): 6 cg x 2 ks2 x 4 mi x 32 lanes, uint4 = {a0,a1,a2,a3}.
//   a0 = (m = mi*16 + lane>>2,      k = (lane&3)*2 + {0,1})
//   a1 = (m+8, same k)   a2 = (m, k+8)   a3 = (m+8, k+8),  c = cg*32+ks2*16+k
// ---------------------------------------------------------------------------
__global__ void __launch_bounds__(256)
kX(const float* __restrict__ x) {
    int sy = blockIdx.x, dxi = blockIdx.y, b = blockIdx.z;
    const float* xr = x + ((size_t)(b * RR + sy) * RR) * CC;
    uint4* dst = g_xAh + ((size_t)(b * 3 + dxi) * RR + sy) * 1536;
#pragma unroll 1
    for (int u = threadIdx.x; u < 1536; u += 256) {
        int lane = u & 31, mi = (u >> 5) & 3, ks2 = (u >> 7) & 1, cg = u >> 8;
        int m0 = mi * 16 + (lane >> 2);
        int cb = cg * 32 + ks2 * 16 + (lane & 3) * 2;
        int sx0 = m0 + dxi - 1, sx1 = sx0 + 8;
        float2 v00 = {0.f, 0.f}, v01 = {0.f, 0.f};
        float2 v10 = {0.f, 0.f}, v11 = {0.f, 0.f};
        if ((unsigned)sx0 < RR) {
            const float* p = xr + (size_t)sx0 * CC + cb;
            v00 = *(const float2*)p;  v01 = *(const float2*)(p + 8);
        }
        if ((unsigned)sx1 < RR) {
            const float* p = xr + (size_t)sx1 * CC + cb;
            v10 = *(const float2*)p;  v11 = *(const float2*)(p + 8);
        }
        __half2 h0 = __floats2half2_rn(v00.x, v00.y);
        __half2 h1 = __floats2half2_rn(v10.x, v10.y);
        __half2 h2 = __floats2half2_rn(v01.x, v01.y);
        __half2 h3 = __floats2half2_rn(v11.x, v11.y);
        uint4 o;
        o.x = *(uint32_t*)&h0;  o.y = *(uint32_t*)&h1;
        o.z = *(uint32_t*)&h2;  o.w = *(uint32_t*)&h3;
        dst[(cg * 8 + ks2 * 4 + mi) * 32 + lane] = o;
    }
}

// ---------------------------------------------------------------------------
// Kernel T: transpose conv1_w for coalesced kW reads (validated)
// ---------------------------------------------------------------------------
__global__ void kT(const float* __restrict__ k1) {
    int i = blockIdx.x * 256 + threadIdx.x;
    if (i >= TAPS * WNN * CC) return;
    int tap = i / (WNN * CC);
    int rc  = i - tap * (WNN * CC);
    g_k1T[i] = k1[(size_t)rc * TAPS + tap];
}

// ---------------------------------------------------------------------------
// Kernel A: pooled depthwise stats -> downchannel logits (validated)
// ---------------------------------------------------------------------------
__global__ void kA(const float* __restrict__ x, const float* __restrict__ k1,
                   const float* __restrict__ dcw, const float* __restrict__ dcb) {
    int b   = blockIdx.x >> 4;
    int win = blockIdx.x & 15;
    int c   = threadIdx.x;
    int rb  = win >> 2, cb = win & 3;
    const float* xp = x + ((size_t)b * RR * RR) * CC + c;
    int base = (rb * WSZ) * RR + cb * WSZ;

    float T = 0.f, r0 = 0.f, r15 = 0.f, c0 = 0.f, c15 = 0.f;
    float e00 = 0.f, e0f = 0.f, ef0 = 0.f, eff = 0.f;
    for (int i = 0; i < 16; i++) {
        float rowacc = 0.f, vj0 = 0.f, vj15 = 0.f;
#pragma unroll
        for (int j = 0; j < 16; j++) {
            float v = xp[(size_t)(base + i * RR + j) * CC];
            rowacc += v;
            if (j == 0)  { c0  += v; vj0  = v; }
            if (j == 15) { c15 += v; vj15 = v; }
        }
        T += rowacc;
        if (i == 0)  { r0  = rowacc; e00 = vj0; e0f = vj15; }
        if (i == 15) { r15 = rowacc; ef0 = vj0; eff = vj15; }
    }

    float Rex[3] = { r15, 0.f, r0 };
    float Cex[3] = { c15, 0.f, c0 };
    const float* kp = k1 + (size_t)(win * CC + c) * TAPS;
    float pooled = 0.f;
#pragma unroll
    for (int p = 0; p < 3; p++) {
#pragma unroll
        for (int q = 0; q < 3; q++) {
            float corner = 0.f;
            if (p == 0 && q == 0) corner = eff;
            if (p == 0 && q == 2) corner = ef0;
            if (p == 2 && q == 0) corner = e0f;
            if (p == 2 && q == 2) corner = e00;
            float S = T - Rex[p] - Cex[q] + corner;
            pooled += kp[p * 3 + q] * S;
        }
    }
    pooled *= (1.f / 256.f);
    float contrib = pooled * dcw[win * CC + c];

    __shared__ float red[192];
    red[c] = contrib;
    __syncthreads();
    for (int s = 96; s >= 6; s >>= 1) {
        if (c < s) red[c] += red[c + s];
        __syncthreads();
    }
    if (c == 0) {
        float tot = red[0] + red[1] + red[2] + red[3] + red[4] + red[5];
        g_t[b * WNN + win] = tot + dcb[win];
    }
}

// ---------------------------------------------------------------------------
// Kernel W: fused MLP + Weff in fp16 m16n8k16 B-fragment order.
// b-frag (per n8, lane): uint4 = { ks2=0:{k0,k0+1}, ks2=0:{k0+8,k0+9},
//                                  ks2=1:{k0,k0+1}, ks2=1:{k0+8,k0+9} }
// with k = (lane&3)*2 within k16-step, n = n8*8 + (lane>>2).
// ---------------------------------------------------------------------------
__global__ void __launch_bounds__(192)
kW(const float* __restrict__ gkb, const float* __restrict__ fw,
   const float* __restrict__ l1w, const float* __restrict__ l1b,
   const float* __restrict__ l2w, const float* __restrict__ l2b,
   const float* __restrict__ gkw) {
    int n = blockIdx.x;          // cout
    int c = threadIdx.x;         // cin = k
    __shared__ float ts[64], hs[256];
    __shared__ float sw_[64], swg[64];

    if (c < 64) ts[c] = g_t[c];
    __syncthreads();
    for (int u = c; u < 256; u += 192) {
        int b = u >> 6, j = u & 63;
        float a = l1b[j];
#pragma unroll
        for (int s = 0; s < 16; s++) a += ts[b * 16 + s] * l1w[j * 16 + s];
        hs[u] = 0.5f * a * (1.f + erff(a * 0.70710678118654752f));
    }
    __syncthreads();
    if (c < 64) {
        int b = c >> 4, s = c & 15;
        float a = l2b[s];
#pragma unroll
        for (int j = 0; j < 64; j++) a += hs[b * 64 + j] * l2w[s * 64 + j];
        float wv = 1.f / (1.f + expf(-a));
        sw_[c] = wv;
        swg[c] = wv * gkw[s];
    }
    __syncthreads();

    float f[17];
    const float* fp = fw + (size_t)n * ((WNN + 1) * CC) + c;
#pragma unroll
    for (int s = 0; s < 17; s++) f[s] = fp[s * CC];
    float g0 = gkb[0];

    int cg  = c >> 5, k32 = c & 31;
    int ks2 = k32 >> 4, kk = k32 & 15;
    int n8  = n >> 3;
    int lane = (n & 7) * 4 + ((kk & 7) >> 1);
    int reg  = ks2 * 2 + (kk >> 3);
    int hidx = kk & 1;
    int wrd  = ((n8 * 32 + lane) * 4 + reg) * 2 + hidx;   // half index in chunk

#pragma unroll 1
    for (int tap = 0; tap < 9; tap++) {
        float kv[16];
        const float* kt = g_k1T + (size_t)tap * WNN * CC + c;
#pragma unroll
        for (int s = 0; s < 16; s++) kv[s] = kt[s * CC];
#pragma unroll
        for (int b = 0; b < 4; b++) {
            float acc = 0.f, ga = g0;
#pragma unroll
            for (int s = 0; s < 16; s++) {
                acc = fmaf(sw_[b * 16 + s] * kv[s], f[s], acc);
                ga  = fmaf(swg[b * 16 + s], kv[s], ga);
            }
            acc = fmaf(ga, f[16], acc);
            g_WBh[((size_t)(b * 9 + tap) * 6 + cg) * 6144 + wrd] =
                __float2half_rn(acc);
        }
    }
}

// ---------------------------------------------------------------------------
// Kernel D: fp16 m16n8k16 mma.sync implicit GEMM, 4 fat warps (64m x 48n).
// No smem, no barriers. A/B fragment-ordered gmem -> registers.
// Per chunk (32k): 8 LDG.128 A (L1-dedup across warps) + 6 LDG.128 B (private),
// 48 MMAs. B double-buffered; next A prefetched to L1 by warp 0.
// ---------------------------------------------------------------------------
__global__ void __launch_bounds__(128, 2)
kD(const float* __restrict__ fb, float* __restrict__ out) {
    int tid  = threadIdx.x;
    int lane = tid & 31;
    int wid  = tid >> 5;
    int b    = blockIdx.y;
    int row  = blockIdx.x;             // image row

    const uint4* WBu = (const uint4*)g_WBh + (size_t)b * TAPS * 6 * 768;

    float acc[4][6][4];
#pragma unroll
    for (int mi = 0; mi < 4; mi++)
#pragma unroll
        for (int ni = 0; ni < 6; ni++)
#pragma unroll
            for (int r = 0; r < 4; r++) acc[mi][ni][r] = 0.f;

    uint4 bfA[6], bfB[6];

    auto loadB = [&](int kc, uint4 (&bf)[6]) {
        int tap = kc / 6, cg = kc - tap * 6;
        const uint4* src = WBu + (tap * 6 + cg) * 768 + wid * 192 + lane;
#pragma unroll
        for (int ni = 0; ni < 6; ni++) bf[ni] = src[ni * 32];
    };
    auto prefA = [&](int kc) {
        if (kc >= 54) return;
        int tap = kc / 6, cg = kc - tap * 6;
        int dy = tap / 3 - 1, dxi = tap % 3;
        int sy = row + dy;
        if ((unsigned)sy >= RR) return;
        const char* p = (const char*)(g_xAh +
            ((size_t)(b * 3 + dxi) * RR + sy) * 1536 + cg * 8 * 32);
        asm volatile("prefetch.global.L1 [%0];" :: "l"(p + lane * 128));
    };
    auto computeChunk = [&](int kc, uint4 (&bf)[6]) {
        int tap = kc / 6, cg = kc - tap * 6;
        int dy = tap / 3 - 1, dxi = tap % 3;
        int sy = row + dy;
        if ((unsigned)sy >= RR) return;          // zero A -> no contribution
        const uint4* ab = g_xAh +
            ((size_t)(b * 3 + dxi) * RR + sy) * 1536 + cg * 8 * 32;
#pragma unroll
        for (int ks2 = 0; ks2 < 2; ks2++) {
            uint32_t af[4][4];
#pragma unroll
            for (int mi = 0; mi < 4; mi++) {
                uint4 v = ab[(ks2 * 4 + mi) * 32 + lane];
                af[mi][0] = v.x; af[mi][1] = v.y;
                af[mi][2] = v.z; af[mi][3] = v.w;
            }
#pragma unroll
            for (int mi = 0; mi < 4; mi++)
#pragma unroll
                for (int ni = 0; ni < 6; ni++) {
                    uint32_t bb[2];
                    bb[0] = ks2 ? bf[ni].z : bf[ni].x;
                    bb[1] = ks2 ? bf[ni].w : bf[ni].y;
                    mma_f16(acc[mi][ni], af[mi], bb);
                }
        }
    };

    loadB(0, bfA);
#pragma unroll 1
    for (int it = 0; it < 27; it++) {
        int kc = it * 2;
        loadB(kc + 1, bfB);
        if (wid == 0) prefA(kc + 1);
        computeChunk(kc, bfA);
        if (kc + 2 < 54) loadB(kc + 2, bfA);
        if (wid == 0) prefA(kc + 2);
        computeChunk(kc + 1, bfB);
    }

    // ---- epilogue: +bias, STG.64 ----
#pragma unroll
    for (int ni = 0; ni < 6; ni++) {
        int co = wid * 48 + ni * 8 + (lane & 3) * 2;
        float bx = fb[co], by = fb[co + 1];
#pragma unroll
        for (int mi = 0; mi < 4; mi++) {
            int m0 = row * 64 + mi * 16 + (lane >> 2);
            size_t o0 = ((size_t)b * RR * RR + m0) * CC + co;
            *(float2*)(out + o0) =
                make_float2(acc[mi][ni][0] + bx, acc[mi][ni][1] + by);
            *(float2*)(out + o0 + (size_t)8 * CC) =
                make_float2(acc[mi][ni][2] + bx, acc[mi][ni][3] + by);
        }
    }
}

// ---------------------------------------------------------------------------
extern "C" void kernel_launch(void* const* d_in, const int* in_sizes, int n_in,
                              void* d_out, int out_size) {
    const float* x   = (const float*)d_in[0];
    const float* k1  = (const float*)d_in[1];
    const float* dcw = (const float*)d_in[2];
    const float* dcb = (const float*)d_in[3];
    const float* l1w = (const float*)d_in[4];
    const float* l1b = (const float*)d_in[5];
    const float* l2w = (const float*)d_in[6];
    const float* l2b = (const float*)d_in[7];
    const float* gkw = (const float*)d_in[8];
    const float* gkb = (const float*)d_in[9];
    const float* fw  = (const float*)d_in[10];
    const float* fb  = (const float*)d_in[11];
    float* out = (float*)d_out;

    static cudaStream_t s1 = nullptr;
    static cudaEvent_t evF = nullptr, evJ = nullptr;
    if (s1 == nullptr) {
        cudaStreamCreateWithFlags(&s1, cudaStreamNonBlocking);
        cudaEventCreateWithFlags(&evF, cudaEventDisableTiming);
        cudaEventCreateWithFlags(&evJ, cudaEventDisableTiming);
    }

    // fork: side chain (kT -> kA -> kW) runs concurrently with kX
    cudaEventRecord(evF, 0);
    cudaStreamWaitEvent(s1, evF, 0);

    kT<<<(TAPS * WNN * CC + 255) / 256, 256, 0, s1>>>(k1);
    kA<<<BB * WNN, CC, 0, s1>>>(x, k1, dcw, dcb);
    kW<<<CC, CC, 0, s1>>>(gkb, fw, l1w, l1b, l2w, l2b, gkw);
    cudaEventRecord(evJ, s1);

    kX<<<dim3(RR, 3, BB), 256>>>(x);

    // join
    cudaStreamWaitEvent(0, evJ, 0);
    dim3 g(RR, BB);   // 64 row-tiles x 4 batches = 256 CTAs
    kD<<<g, 128>>>(fb, out);
}

// round 14
// speedup vs baseline: 1.8168x; 1.0296x over previous
#include <cuda_runtime.h>
#include <cuda_fp16.h>
#include <math.h>
#include <cstdint>

#define BB   4
#define RR   64
#define CC   192
#define WNN  16
#define WSZ  16
#define TAPS 9

// ---------------- device scratch ----------------
__device__ float  g_t[BB * WNN];
__device__ uint4  g_xAh[(size_t)BB * 3 * RR * 1536];   // A fp16 frag-order
__device__ __half g_WBh[(size_t)BB * TAPS * 6 * 6144]; // B fp16 frag-order
__device__ float  g_k1T[TAPS * WNN * CC];              // k1 transposed [tap][s][c]

__device__ __forceinline__ void mma_f16(float* d, const uint32_t* a, const uint32_t* b) {
    asm volatile(
        "mma.sync.aligned.m16n8k16.row.col.f32.f16.f16.f32 "
        "{%0,%1,%2,%3}, {%4,%5,%6,%7}, {%8,%9}, {%0,%1,%2,%3};"
        : "+f"(d[0]), "+f"(d[1]), "+f"(d[2]), "+f"(d[3])
        : "r"(a[0]), "r"(a[1]), "r"(a[2]), "r"(a[3]), "r"(b[0]), "r"(b[1]));
}

// ---------------------------------------------------------------------------
// Kernel X: build fp16 A operand in m16n8k16 fragment order (validated R13)
// ---------------------------------------------------------------------------
__global__ void __launch_bounds__(256)
kX(const float* __restrict__ x) {
    int sy = blockIdx.x, dxi = blockIdx.y, b = blockIdx.z;
    const float* xr = x + ((size_t)(b * RR + sy) * RR) * CC;
    uint4* dst = g_xAh + ((size_t)(b * 3 + dxi) * RR + sy) * 1536;
#pragma unroll 1
    for (int u = threadIdx.x; u < 1536; u += 256) {
        int lane = u & 31, mi = (u >> 5) & 3, ks2 = (u >> 7) & 1, cg = u >> 8;
        int m0 = mi * 16 + (lane >> 2);
        int cb = cg * 32 + ks2 * 16 + (lane & 3) * 2;
        int sx0 = m0 + dxi - 1, sx1 = sx0 + 8;
        float2 v00 = {0.f, 0.f}, v01 = {0.f, 0.f};
        float2 v10 = {0.f, 0.f}, v11 = {0.f, 0.f};
        if ((unsigned)sx0 < RR) {
            const float* p = xr + (size_t)sx0 * CC + cb;
            v00 = *(const float2*)p;  v01 = *(const float2*)(p + 8);
        }
        if ((unsigned)sx1 < RR) {
            const float* p = xr + (size_t)sx1 * CC + cb;
            v10 = *(const float2*)p;  v11 = *(const float2*)(p + 8);
        }
        __half2 h0 = __floats2half2_rn(v00.x, v00.y);
        __half2 h1 = __floats2half2_rn(v10.x, v10.y);
        __half2 h2 = __floats2half2_rn(v01.x, v01.y);
        __half2 h3 = __floats2half2_rn(v11.x, v11.y);
        uint4 o;
        o.x = *(uint32_t*)&h0;  o.y = *(uint32_t*)&h1;
        o.z = *(uint32_t*)&h2;  o.w = *(uint32_t*)&h3;
        dst[(cg * 8 + ks2 * 4 + mi) * 32 + lane] = o;
    }
}

// ---------------------------------------------------------------------------
// Kernel T: transpose conv1_w (validated)
// ---------------------------------------------------------------------------
__global__ void kT(const float* __restrict__ k1) {
    int i = blockIdx.x * 256 + threadIdx.x;
    if (i >= TAPS * WNN * CC) return;
    int tap = i / (WNN * CC);
    int rc  = i - tap * (WNN * CC);
    g_k1T[i] = k1[(size_t)rc * TAPS + tap];
}

// ---------------------------------------------------------------------------
// Kernel A: pooled depthwise stats, 4-way row-split (768 thr: group g = rows
// 4g..4g+3). Partials combined in smem, then the validated tap/corner math.
// ---------------------------------------------------------------------------
__global__ void __launch_bounds__(768)
kA(const float* __restrict__ x, const float* __restrict__ k1,
   const float* __restrict__ dcw, const float* __restrict__ dcb) {
    int b   = blockIdx.x >> 4;
    int win = blockIdx.x & 15;
    int g   = threadIdx.x / 192;
    int c   = threadIdx.x % 192;
    int rb  = win >> 2, cb = win & 3;
    const float* xp = x + ((size_t)b * RR * RR) * CC + c;
    int base = (rb * WSZ) * RR + cb * WSZ;

    float Tp = 0.f, c0p = 0.f, c15p = 0.f;
    float r0 = 0.f, r15 = 0.f, e00 = 0.f, e0f = 0.f, ef0 = 0.f, eff = 0.f;
#pragma unroll
    for (int ii = 0; ii < 4; ii++) {
        int i = g * 4 + ii;
        float rowacc = 0.f, vj0 = 0.f, vj15 = 0.f;
#pragma unroll
        for (int j = 0; j < 16; j++) {
            float v = xp[(size_t)(base + i * RR + j) * CC];
            rowacc += v;
            if (j == 0)  { c0p  += v; vj0  = v; }
            if (j == 15) { c15p += v; vj15 = v; }
        }
        Tp += rowacc;
        if (i == 0)  { r0  = rowacc; e00 = vj0; e0f = vj15; }
        if (i == 15) { r15 = rowacc; ef0 = vj0; eff = vj15; }
    }

    __shared__ float sT[4][192], sc0[4][192], sc15[4][192];
    __shared__ float sr0[192], sr15[192], sE[4][192];
    __shared__ float red[192];
    sT[g][c] = Tp;  sc0[g][c] = c0p;  sc15[g][c] = c15p;
    if (g == 0) { sr0[c] = r0;  sE[0][c] = e00; sE[1][c] = e0f; }
    if (g == 3) { sr15[c] = r15; sE[2][c] = ef0; sE[3][c] = eff; }
    __syncthreads();

    if (g == 0) {
        float T   = sT[0][c] + sT[1][c] + sT[2][c] + sT[3][c];
        float c0  = sc0[0][c] + sc0[1][c] + sc0[2][c] + sc0[3][c];
        float c15 = sc15[0][c] + sc15[1][c] + sc15[2][c] + sc15[3][c];
        float Rex[3] = { sr15[c], 0.f, sr0[c] };
        float Cex[3] = { c15, 0.f, c0 };
        float e00v = sE[0][c], e0fv = sE[1][c], ef0v = sE[2][c], effv = sE[3][c];
        const float* kp = k1 + (size_t)(win * CC + c) * TAPS;
        float pooled = 0.f;
#pragma unroll
        for (int p = 0; p < 3; p++) {
#pragma unroll
            for (int q = 0; q < 3; q++) {
                float corner = 0.f;
                if (p == 0 && q == 0) corner = effv;
                if (p == 0 && q == 2) corner = ef0v;
                if (p == 2 && q == 0) corner = e0fv;
                if (p == 2 && q == 2) corner = e00v;
                float S = T - Rex[p] - Cex[q] + corner;
                pooled += kp[p * 3 + q] * S;
            }
        }
        pooled *= (1.f / 256.f);
        red[c] = pooled * dcw[win * CC + c];
    }
    __syncthreads();
    for (int s = 96; s >= 6; s >>= 1) {
        if (g == 0 && c < s) red[c] += red[c + s];
        __syncthreads();
    }
    if (threadIdx.x == 0) {
        float tot = red[0] + red[1] + red[2] + red[3] + red[4] + red[5];
        g_t[b * WNN + win] = tot + dcb[win];
    }
}

// ---------------------------------------------------------------------------
// Kernel W: fused MLP + Weff in fp16 B-fragment order (validated R13)
// ---------------------------------------------------------------------------
__global__ void __launch_bounds__(192)
kW(const float* __restrict__ gkb, const float* __restrict__ fw,
   const float* __restrict__ l1w, const float* __restrict__ l1b,
   const float* __restrict__ l2w, const float* __restrict__ l2b,
   const float* __restrict__ gkw) {
    int n = blockIdx.x;          // cout
    int c = threadIdx.x;         // cin = k
    __shared__ float ts[64], hs[256];
    __shared__ float sw_[64], swg[64];

    if (c < 64) ts[c] = g_t[c];
    __syncthreads();
    for (int u = c; u < 256; u += 192) {
        int b = u >> 6, j = u & 63;
        float a = l1b[j];
#pragma unroll
        for (int s = 0; s < 16; s++) a += ts[b * 16 + s] * l1w[j * 16 + s];
        hs[u] = 0.5f * a * (1.f + erff(a * 0.70710678118654752f));
    }
    __syncthreads();
    if (c < 64) {
        int b = c >> 4, s = c & 15;
        float a = l2b[s];
#pragma unroll
        for (int j = 0; j < 64; j++) a += hs[b * 64 + j] * l2w[s * 64 + j];
        float wv = 1.f / (1.f + expf(-a));
        sw_[c] = wv;
        swg[c] = wv * gkw[s];
    }
    __syncthreads();

    float f[17];
    const float* fp = fw + (size_t)n * ((WNN + 1) * CC) + c;
#pragma unroll
    for (int s = 0; s < 17; s++) f[s] = fp[s * CC];
    float g0 = gkb[0];

    int cg  = c >> 5, k32 = c & 31;
    int ks2 = k32 >> 4, kk = k32 & 15;
    int n8  = n >> 3;
    int lane = (n & 7) * 4 + ((kk & 7) >> 1);
    int reg  = ks2 * 2 + (kk >> 3);
    int hidx = kk & 1;
    int wrd  = ((n8 * 32 + lane) * 4 + reg) * 2 + hidx;

#pragma unroll 1
    for (int tap = 0; tap < 9; tap++) {
        float kv[16];
        const float* kt = g_k1T + (size_t)tap * WNN * CC + c;
#pragma unroll
        for (int s = 0; s < 16; s++) kv[s] = kt[s * CC];
#pragma unroll
        for (int b = 0; b < 4; b++) {
            float acc = 0.f, ga = g0;
#pragma unroll
            for (int s = 0; s < 16; s++) {
                acc = fmaf(sw_[b * 16 + s] * kv[s], f[s], acc);
                ga  = fmaf(swg[b * 16 + s], kv[s], ga);
            }
            acc = fmaf(ga, f[16], acc);
            g_WBh[((size_t)(b * 9 + tap) * 6 + cg) * 6144 + wrd] =
                __float2half_rn(acc);
        }
    }
}

// ---------------------------------------------------------------------------
// Kernel D: fp16 m16n8k16 implicit GEMM, N-split.
// CTA: M=64 x N=96 (nq half), 4 warps of 64m x 24n, acc 48 regs.
// Grid 512 -> occupancy 4 -> 16 warps/SM. B L2 traffic unchanged; A dup x2.
// No smem, no barriers; B reg-double-buffered.
// ---------------------------------------------------------------------------
__global__ void __launch_bounds__(128, 4)
kD(const float* __restrict__ fb, float* __restrict__ out) {
    int tid  = threadIdx.x;
    int lane = tid & 31;
    int wid  = tid >> 5;
    int row  = blockIdx.x;             // image row
    int nq   = blockIdx.y;             // n half (0/1)
    int b    = blockIdx.z;

    const uint4* WBu = (const uint4*)g_WBh + (size_t)b * TAPS * 6 * 768;
    int n8base = nq * 12 + wid * 3;

    float acc[4][3][4];
#pragma unroll
    for (int mi = 0; mi < 4; mi++)
#pragma unroll
        for (int ni = 0; ni < 3; ni++)
#pragma unroll
            for (int r = 0; r < 4; r++) acc[mi][ni][r] = 0.f;

    uint4 bfA[3], bfB[3];

    auto loadB = [&](int kc, uint4 (&bf)[3]) {
        int tap = kc / 6, cg = kc - tap * 6;
        const uint4* src = WBu + (tap * 6 + cg) * 768 + n8base * 32 + lane;
#pragma unroll
        for (int ni = 0; ni < 3; ni++) bf[ni] = src[ni * 32];
    };
    auto prefA = [&](int kc) {
        if (kc >= 54) return;
        int tap = kc / 6, cg = kc - tap * 6;
        int dy = tap / 3 - 1, dxi = tap % 3;
        int sy = row + dy;
        if ((unsigned)sy >= RR) return;
        const char* p = (const char*)(g_xAh +
            ((size_t)(b * 3 + dxi) * RR + sy) * 1536 + cg * 8 * 32);
        asm volatile("prefetch.global.L1 [%0];" :: "l"(p + lane * 128));
    };
    auto computeChunk = [&](int kc, uint4 (&bf)[3]) {
        int tap = kc / 6, cg = kc - tap * 6;
        int dy = tap / 3 - 1, dxi = tap % 3;
        int sy = row + dy;
        if ((unsigned)sy >= RR) return;          // zero A -> no contribution
        const uint4* ab = g_xAh +
            ((size_t)(b * 3 + dxi) * RR + sy) * 1536 + cg * 8 * 32;
#pragma unroll
        for (int ks2 = 0; ks2 < 2; ks2++) {
            uint32_t af[4][4];
#pragma unroll
            for (int mi = 0; mi < 4; mi++) {
                uint4 v = ab[(ks2 * 4 + mi) * 32 + lane];
                af[mi][0] = v.x; af[mi][1] = v.y;
                af[mi][2] = v.z; af[mi][3] = v.w;
            }
#pragma unroll
            for (int mi = 0; mi < 4; mi++)
#pragma unroll
                for (int ni = 0; ni < 3; ni++) {
                    uint32_t bb[2];
                    bb[0] = ks2 ? bf[ni].z : bf[ni].x;
                    bb[1] = ks2 ? bf[ni].w : bf[ni].y;
                    mma_f16(acc[mi][ni], af[mi], bb);
                }
        }
    };

    loadB(0, bfA);
#pragma unroll 1
    for (int it = 0; it < 27; it++) {
        int kc = it * 2;
        loadB(kc + 1, bfB);
        if (wid == 0) prefA(kc + 1);
        computeChunk(kc, bfA);
        if (kc + 2 < 54) loadB(kc + 2, bfA);
        if (wid == 0) prefA(kc + 2);
        computeChunk(kc + 1, bfB);
    }

    // ---- epilogue: +bias, STG.64 ----
#pragma unroll
    for (int ni = 0; ni < 3; ni++) {
        int co = nq * 96 + wid * 24 + ni * 8 + (lane & 3) * 2;
        float bx = fb[co], by = fb[co + 1];
#pragma unroll
        for (int mi = 0; mi < 4; mi++) {
            int m0 = row * 64 + mi * 16 + (lane >> 2);
            size_t o0 = ((size_t)b * RR * RR + m0) * CC + co;
            *(float2*)(out + o0) =
                make_float2(acc[mi][ni][0] + bx, acc[mi][ni][1] + by);
            *(float2*)(out + o0 + (size_t)8 * CC) =
                make_float2(acc[mi][ni][2] + bx, acc[mi][ni][3] + by);
        }
    }
}

// ---------------------------------------------------------------------------
extern "C" void kernel_launch(void* const* d_in, const int* in_sizes, int n_in,
                              void* d_out, int out_size) {
    const float* x   = (const float*)d_in[0];
    const float* k1  = (const float*)d_in[1];
    const float* dcw = (const float*)d_in[2];
    const float* dcb = (const float*)d_in[3];
    const float* l1w = (const float*)d_in[4];
    const float* l1b = (const float*)d_in[5];
    const float* l2w = (const float*)d_in[6];
    const float* l2b = (const float*)d_in[7];
    const float* gkw = (const float*)d_in[8];
    const float* gkb = (const float*)d_in[9];
    const float* fw  = (const float*)d_in[10];
    const float* fb  = (const float*)d_in[11];
    float* out = (float*)d_out;

    static cudaStream_t s1 = nullptr;
    static cudaEvent_t evF = nullptr, evJ = nullptr;
    if (s1 == nullptr) {
        cudaStreamCreateWithFlags(&s1, cudaStreamNonBlocking);
        cudaEventCreateWithFlags(&evF, cudaEventDisableTiming);
        cudaEventCreateWithFlags(&evJ, cudaEventDisableTiming);
    }

    // fork: side chain (kT -> kA -> kW) runs concurrently with kX
    cudaEventRecord(evF, 0);
    cudaStreamWaitEvent(s1, evF, 0);

    kT<<<(TAPS * WNN * CC + 255) / 256, 256, 0, s1>>>(k1);
    kA<<<BB * WNN, 768, 0, s1>>>(x, k1, dcw, dcb);
    kW<<<CC, CC, 0, s1>>>(gkb, fw, l1w, l1b, l2w, l2b, gkw);
    cudaEventRecord(evJ, s1);

    kX<<<dim3(RR, 3, BB), 256>>>(x);

    // join
    cudaStreamWaitEvent(0, evJ, 0);
    dim3 g(RR, 2, BB);   // 64 rows x 2 n-halves x 4 batches = 512 CTAs
    kD<<<g, 128>>>(fb, out);
}

// round 15
// speedup vs baseline: 1.8621x; 1.0249x over previous
#include <cuda_runtime.h>
#include <cuda_fp16.h>
#include <math.h>
#include <cstdint>

#define BB   4
#define RR   64
#define CC   192
#define WNN  16
#define WSZ  16
#define TAPS 9

// ---------------- device scratch ----------------
__device__ float  g_t[BB * WNN];
__device__ uint4  g_xAh[(size_t)BB * 3 * RR * 1536];   // A fp16 frag-order
__device__ __half g_WBh[(size_t)BB * TAPS * 6 * 6144]; // B fp16 frag-order
__device__ float  g_k1T[TAPS * WNN * CC];              // k1 transposed [tap][s][c]

__device__ __forceinline__ void mma_f16(float* d, const uint32_t* a, const uint32_t* b) {
    asm volatile(
        "mma.sync.aligned.m16n8k16.row.col.f32.f16.f16.f32 "
        "{%0,%1,%2,%3}, {%4,%5,%6,%7}, {%8,%9}, {%0,%1,%2,%3};"
        : "+f"(d[0]), "+f"(d[1]), "+f"(d[2]), "+f"(d[3])
        : "r"(a[0]), "r"(a[1]), "r"(a[2]), "r"(a[3]), "r"(b[0]), "r"(b[1]));
}

// ---------------------------------------------------------------------------
// Kernel X: build fp16 A operand in m16n8k16 fragment order.
// Fully unrolled (6 independent items/thread, 24 loads in flight).
// ---------------------------------------------------------------------------
__global__ void __launch_bounds__(256)
kX(const float* __restrict__ x) {
    int sy = blockIdx.x, dxi = blockIdx.y, b = blockIdx.z;
    const float* xr = x + ((size_t)(b * RR + sy) * RR) * CC;
    uint4* dst = g_xAh + ((size_t)(b * 3 + dxi) * RR + sy) * 1536;
#pragma unroll
    for (int it = 0; it < 6; it++) {
        int u = threadIdx.x + it * 256;
        int lane = u & 31, mi = (u >> 5) & 3, ks2 = (u >> 7) & 1, cg = u >> 8;
        int m0 = mi * 16 + (lane >> 2);
        int cb = cg * 32 + ks2 * 16 + (lane & 3) * 2;
        int sx0 = m0 + dxi - 1, sx1 = sx0 + 8;
        float2 v00 = {0.f, 0.f}, v01 = {0.f, 0.f};
        float2 v10 = {0.f, 0.f}, v11 = {0.f, 0.f};
        if ((unsigned)sx0 < RR) {
            const float* p = xr + (size_t)sx0 * CC + cb;
            v00 = *(const float2*)p;  v01 = *(const float2*)(p + 8);
        }
        if ((unsigned)sx1 < RR) {
            const float* p = xr + (size_t)sx1 * CC + cb;
            v10 = *(const float2*)p;  v11 = *(const float2*)(p + 8);
        }
        __half2 h0 = __floats2half2_rn(v00.x, v00.y);
        __half2 h1 = __floats2half2_rn(v10.x, v10.y);
        __half2 h2 = __floats2half2_rn(v01.x, v01.y);
        __half2 h3 = __floats2half2_rn(v11.x, v11.y);
        uint4 o;
        o.x = *(uint32_t*)&h0;  o.y = *(uint32_t*)&h1;
        o.z = *(uint32_t*)&h2;  o.w = *(uint32_t*)&h3;
        dst[(cg * 8 + ks2 * 4 + mi) * 32 + lane] = o;
    }
}

// ---------------------------------------------------------------------------
// Kernel T: transpose conv1_w (validated)
// ---------------------------------------------------------------------------
__global__ void kT(const float* __restrict__ k1) {
    int i = blockIdx.x * 256 + threadIdx.x;
    if (i >= TAPS * WNN * CC) return;
    int tap = i / (WNN * CC);
    int rc  = i - tap * (WNN * CC);
    g_k1T[i] = k1[(size_t)rc * TAPS + tap];
}

// ---------------------------------------------------------------------------
// Kernel A: pooled depthwise stats, 4-way row-split (validated R14)
// ---------------------------------------------------------------------------
__global__ void __launch_bounds__(768)
kA(const float* __restrict__ x, const float* __restrict__ k1,
   const float* __restrict__ dcw, const float* __restrict__ dcb) {
    int b   = blockIdx.x >> 4;
    int win = blockIdx.x & 15;
    int g   = threadIdx.x / 192;
    int c   = threadIdx.x % 192;
    int rb  = win >> 2, cb = win & 3;
    const float* xp = x + ((size_t)b * RR * RR) * CC + c;
    int base = (rb * WSZ) * RR + cb * WSZ;

    float Tp = 0.f, c0p = 0.f, c15p = 0.f;
    float r0 = 0.f, r15 = 0.f, e00 = 0.f, e0f = 0.f, ef0 = 0.f, eff = 0.f;
#pragma unroll
    for (int ii = 0; ii < 4; ii++) {
        int i = g * 4 + ii;
        float rowacc = 0.f, vj0 = 0.f, vj15 = 0.f;
#pragma unroll
        for (int j = 0; j < 16; j++) {
            float v = xp[(size_t)(base + i * RR + j) * CC];
            rowacc += v;
            if (j == 0)  { c0p  += v; vj0  = v; }
            if (j == 15) { c15p += v; vj15 = v; }
        }
        Tp += rowacc;
        if (i == 0)  { r0  = rowacc; e00 = vj0; e0f = vj15; }
        if (i == 15) { r15 = rowacc; ef0 = vj0; eff = vj15; }
    }

    __shared__ float sT[4][192], sc0[4][192], sc15[4][192];
    __shared__ float sr0[192], sr15[192], sE[4][192];
    __shared__ float red[192];
    sT[g][c] = Tp;  sc0[g][c] = c0p;  sc15[g][c] = c15p;
    if (g == 0) { sr0[c] = r0;  sE[0][c] = e00; sE[1][c] = e0f; }
    if (g == 3) { sr15[c] = r15; sE[2][c] = ef0; sE[3][c] = eff; }
    __syncthreads();

    if (g == 0) {
        float T   = sT[0][c] + sT[1][c] + sT[2][c] + sT[3][c];
        float c0  = sc0[0][c] + sc0[1][c] + sc0[2][c] + sc0[3][c];
        float c15 = sc15[0][c] + sc15[1][c] + sc15[2][c] + sc15[3][c];
        float Rex[3] = { sr15[c], 0.f, sr0[c] };
        float Cex[3] = { c15, 0.f, c0 };
        float e00v = sE[0][c], e0fv = sE[1][c], ef0v = sE[2][c], effv = sE[3][c];
        const float* kp = k1 + (size_t)(win * CC + c) * TAPS;
        float pooled = 0.f;
#pragma unroll
        for (int p = 0; p < 3; p++) {
#pragma unroll
            for (int q = 0; q < 3; q++) {
                float corner = 0.f;
                if (p == 0 && q == 0) corner = effv;
                if (p == 0 && q == 2) corner = ef0v;
                if (p == 2 && q == 0) corner = e0fv;
                if (p == 2 && q == 2) corner = e00v;
                float S = T - Rex[p] - Cex[q] + corner;
                pooled += kp[p * 3 + q] * S;
            }
        }
        pooled *= (1.f / 256.f);
        red[c] = pooled * dcw[win * CC + c];
    }
    __syncthreads();
    for (int s = 96; s >= 6; s >>= 1) {
        if (g == 0 && c < s) red[c] += red[c + s];
        __syncthreads();
    }
    if (threadIdx.x == 0) {
        float tot = red[0] + red[1] + red[2] + red[3] + red[4] + red[5];
        g_t[b * WNN + win] = tot + dcb[win];
    }
}

// ---------------------------------------------------------------------------
// Kernel W: fused MLP + Weff in fp16 B-fragment order (validated R13)
// ---------------------------------------------------------------------------
__global__ void __launch_bounds__(192)
kW(const float* __restrict__ gkb, const float* __restrict__ fw,
   const float* __restrict__ l1w, const float* __restrict__ l1b,
   const float* __restrict__ l2w, const float* __restrict__ l2b,
   const float* __restrict__ gkw) {
    int n = blockIdx.x;          // cout
    int c = threadIdx.x;         // cin = k
    __shared__ float ts[64], hs[256];
    __shared__ float sw_[64], swg[64];

    if (c < 64) ts[c] = g_t[c];
    __syncthreads();
    for (int u = c; u < 256; u += 192) {
        int b = u >> 6, j = u & 63;
        float a = l1b[j];
#pragma unroll
        for (int s = 0; s < 16; s++) a += ts[b * 16 + s] * l1w[j * 16 + s];
        hs[u] = 0.5f * a * (1.f + erff(a * 0.70710678118654752f));
    }
    __syncthreads();
    if (c < 64) {
        int b = c >> 4, s = c & 15;
        float a = l2b[s];
#pragma unroll
        for (int j = 0; j < 64; j++) a += hs[b * 64 + j] * l2w[s * 64 + j];
        float wv = 1.f / (1.f + expf(-a));
        sw_[c] = wv;
        swg[c] = wv * gkw[s];
    }
    __syncthreads();

    float f[17];
    const float* fp = fw + (size_t)n * ((WNN + 1) * CC) + c;
#pragma unroll
    for (int s = 0; s < 17; s++) f[s] = fp[s * CC];
    float g0 = gkb[0];

    int cg  = c >> 5, k32 = c & 31;
    int ks2 = k32 >> 4, kk = k32 & 15;
    int n8  = n >> 3;
    int lane = (n & 7) * 4 + ((kk & 7) >> 1);
    int reg  = ks2 * 2 + (kk >> 3);
    int hidx = kk & 1;
    int wrd  = ((n8 * 32 + lane) * 4 + reg) * 2 + hidx;

#pragma unroll 1
    for (int tap = 0; tap < 9; tap++) {
        float kv[16];
        const float* kt = g_k1T + (size_t)tap * WNN * CC + c;
#pragma unroll
        for (int s = 0; s < 16; s++) kv[s] = kt[s * CC];
#pragma unroll
        for (int b = 0; b < 4; b++) {
            float acc = 0.f, ga = g0;
#pragma unroll
            for (int s = 0; s < 16; s++) {
                acc = fmaf(sw_[b * 16 + s] * kv[s], f[s], acc);
                ga  = fmaf(swg[b * 16 + s], kv[s], ga);
            }
            acc = fmaf(ga, f[16], acc);
            g_WBh[((size_t)(b * 9 + tap) * 6 + cg) * 6144 + wrd] =
                __float2half_rn(acc);
        }
    }
}

// ---------------------------------------------------------------------------
// Kernel D: fp16 m16n8k16 implicit GEMM, N-split.
// CTA: M=64 x N=96, 4 warps of 64m x 24n. Grid 512, occupancy 4.
// Full chunk's A (8 x LDG.128) batched before MMAs; B reg-double-buffered.
// ---------------------------------------------------------------------------
__global__ void __launch_bounds__(128, 4)
kD(const float* __restrict__ fb, float* __restrict__ out) {
    int tid  = threadIdx.x;
    int lane = tid & 31;
    int wid  = tid >> 5;
    int row  = blockIdx.x;             // image row
    int nq   = blockIdx.y;             // n half (0/1)
    int b    = blockIdx.z;

    const uint4* WBu = (const uint4*)g_WBh + (size_t)b * TAPS * 6 * 768;
    int n8base = nq * 12 + wid * 3;

    float acc[4][3][4];
#pragma unroll
    for (int mi = 0; mi < 4; mi++)
#pragma unroll
        for (int ni = 0; ni < 3; ni++)
#pragma unroll
            for (int r = 0; r < 4; r++) acc[mi][ni][r] = 0.f;

    uint4 bfA[3], bfB[3];

    auto loadB = [&](int kc, uint4 (&bf)[3]) {
        int tap = kc / 6, cg = kc - tap * 6;
        const uint4* src = WBu + (tap * 6 + cg) * 768 + n8base * 32 + lane;
#pragma unroll
        for (int ni = 0; ni < 3; ni++) bf[ni] = src[ni * 32];
    };
    auto prefA = [&](int kc) {
        if (kc >= 54) return;
        int tap = kc / 6, cg = kc - tap * 6;
        int dy = tap / 3 - 1, dxi = tap % 3;
        int sy = row + dy;
        if ((unsigned)sy >= RR) return;
        const char* p = (const char*)(g_xAh +
            ((size_t)(b * 3 + dxi) * RR + sy) * 1536 + cg * 8 * 32);
        asm volatile("prefetch.global.L1 [%0];" :: "l"(p + lane * 128));
    };
    auto computeChunk = [&](int kc, uint4 (&bf)[3]) {
        int tap = kc / 6, cg = kc - tap * 6;
        int dy = tap / 3 - 1, dxi = tap % 3;
        int sy = row + dy;
        if ((unsigned)sy >= RR) return;          // zero A -> no contribution
        const uint4* ab = g_xAh +
            ((size_t)(b * 3 + dxi) * RR + sy) * 1536 + cg * 8 * 32;
        uint4 av[8];
#pragma unroll
        for (int q = 0; q < 8; q++) av[q] = ab[q * 32 + lane];   // 8 LDG in flight
#pragma unroll
        for (int ks2 = 0; ks2 < 2; ks2++) {
#pragma unroll
            for (int mi = 0; mi < 4; mi++) {
                uint32_t af[4];
                uint4 v = av[ks2 * 4 + mi];
                af[0] = v.x; af[1] = v.y; af[2] = v.z; af[3] = v.w;
#pragma unroll
                for (int ni = 0; ni < 3; ni++) {
                    uint32_t bb[2];
                    bb[0] = ks2 ? bf[ni].z : bf[ni].x;
                    bb[1] = ks2 ? bf[ni].w : bf[ni].y;
                    mma_f16(acc[mi][ni], af, bb);
                }
            }
        }
    };

    loadB(0, bfA);
#pragma unroll 1
    for (int it = 0; it < 27; it++) {
        int kc = it * 2;
        loadB(kc + 1, bfB);
        if (wid == 0) prefA(kc + 1);
        computeChunk(kc, bfA);
        if (kc + 2 < 54) loadB(kc + 2, bfA);
        if (wid == 0) prefA(kc + 2);
        computeChunk(kc + 1, bfB);
    }

    // ---- epilogue: +bias, STG.64 ----
#pragma unroll
    for (int ni = 0; ni < 3; ni++) {
        int co = nq * 96 + wid * 24 + ni * 8 + (lane & 3) * 2;
        float bx = fb[co], by = fb[co + 1];
#pragma unroll
        for (int mi = 0; mi < 4; mi++) {
            int m0 = row * 64 + mi * 16 + (lane >> 2);
            size_t o0 = ((size_t)b * RR * RR + m0) * CC + co;
            *(float2*)(out + o0) =
                make_float2(acc[mi][ni][0] + bx, acc[mi][ni][1] + by);
            *(float2*)(out + o0 + (size_t)8 * CC) =
                make_float2(acc[mi][ni][2] + bx, acc[mi][ni][3] + by);
        }
    }
}

// ---------------------------------------------------------------------------
extern "C" void kernel_launch(void* const* d_in, const int* in_sizes, int n_in,
                              void* d_out, int out_size) {
    const float* x   = (const float*)d_in[0];
    const float* k1  = (const float*)d_in[1];
    const float* dcw = (const float*)d_in[2];
    const float* dcb = (const float*)d_in[3];
    const float* l1w = (const float*)d_in[4];
    const float* l1b = (const float*)d_in[5];
    const float* l2w = (const float*)d_in[6];
    const float* l2b = (const float*)d_in[7];
    const float* gkw = (const float*)d_in[8];
    const float* gkb = (const float*)d_in[9];
    const float* fw  = (const float*)d_in[10];
    const float* fb  = (const float*)d_in[11];
    float* out = (float*)d_out;

    static cudaStream_t s1 = nullptr;
    static cudaEvent_t evF = nullptr, evJ = nullptr;
    if (s1 == nullptr) {
        cudaStreamCreateWithFlags(&s1, cudaStreamNonBlocking);
        cudaEventCreateWithFlags(&evF, cudaEventDisableTiming);
        cudaEventCreateWithFlags(&evJ, cudaEventDisableTiming);
    }

    // fork: side chain (kT -> kA -> kW) runs concurrently with kX
    cudaEventRecord(evF, 0);
    cudaStreamWaitEvent(s1, evF, 0);

    kT<<<(TAPS * WNN * CC + 255) / 256, 256, 0, s1>>>(k1);
    kA<<<BB * WNN, 768, 0, s1>>>(x, k1, dcw, dcb);
    kW<<<CC, CC, 0, s1>>>(gkb, fw, l1w, l1b, l2w, l2b, gkw);
    cudaEventRecord(evJ, s1);

    kX<<<dim3(RR, 3, BB), 256>>>(x);

    // join
    cudaStreamWaitEvent(0, evJ, 0);
    dim3 g(RR, 2, BB);   // 64 rows x 2 n-halves x 4 batches = 512 CTAs
    kD<<<g, 128>>>(fb, out);
}

// round 16
// speedup vs baseline: 1.8932x; 1.0167x over previous
#include <cuda_runtime.h>
#include <cuda_fp16.h>
#include <math.h>
#include <cstdint>

#define BB   4
#define RR   64
#define CC   192
#define WNN  16
#define WSZ  16
#define TAPS 9

// ---------------- device scratch ----------------
__device__ float  g_t[BB * WNN];
__device__ uint4  g_xAh[(size_t)BB * 3 * RR * 1536];   // A fp16 frag-order
__device__ __half g_WBh[(size_t)BB * TAPS * 6 * 6144]; // B fp16 frag-order
__device__ float  g_k1T[TAPS * WNN * CC];              // k1 transposed [tap][s][c]

__device__ __forceinline__ void mma_f16(float* d, const uint32_t* a, const uint32_t* b) {
    asm volatile(
        "mma.sync.aligned.m16n8k16.row.col.f32.f16.f16.f32 "
        "{%0,%1,%2,%3}, {%4,%5,%6,%7}, {%8,%9}, {%0,%1,%2,%3};"
        : "+f"(d[0]), "+f"(d[1]), "+f"(d[2]), "+f"(d[3])
        : "r"(a[0]), "r"(a[1]), "r"(a[2]), "r"(a[3]), "r"(b[0]), "r"(b[1]));
}

// ---------------------------------------------------------------------------
// Kernel X: fp16 A fragments for all 3 dx shifts from one smem-staged row.
// Block = (b, sy). Row loaded once, coalesced; shifts resolved in smem.
// ---------------------------------------------------------------------------
#define XPAD 194

__global__ void __launch_bounds__(256)
kX(const float* __restrict__ x) {
    __shared__ float sr[RR][XPAD];
    int sy = blockIdx.x & 63;
    int b  = blockIdx.x >> 6;

    const float4* xr4 = (const float4*)(x + (size_t)(b * RR + sy) * RR * CC);
#pragma unroll
    for (int it = 0; it < 12; it++) {
        int i = threadIdx.x + it * 256;           // 3072 float4 total
        int px = i / 48, f4 = i - px * 48;
        float4 v = xr4[i];
        sr[px][f4 * 4 + 0] = v.x;
        sr[px][f4 * 4 + 1] = v.y;
        sr[px][f4 * 4 + 2] = v.z;
        sr[px][f4 * 4 + 3] = v.w;
    }
    __syncthreads();

    int lane = threadIdx.x & 31;
    int mi   = (threadIdx.x >> 5) & 3;            // warp-derived constants
    int wh   = threadIdx.x >> 7;                  // 0/1 -> handles (ks2) half
    int m0   = mi * 16 + (lane >> 2);
    int cbj  = (lane & 3) * 2;

#pragma unroll
    for (int dxi = 0; dxi < 3; dxi++) {
        uint4* dst = g_xAh + ((size_t)(b * 3 + dxi) * RR + sy) * 1536;
        int sx0 = m0 + dxi - 1, sx1 = sx0 + 8;
        bool ok0 = (unsigned)sx0 < RR, ok1 = (unsigned)sx1 < RR;
#pragma unroll
        for (int it = 0; it < 3; it++) {          // cg pairs: this thread does
            int cg  = it * 2 + (wh ? 1 : 0) - 0;  // split 6 cg x 2 ks2 = 12 units
            int ks2 = 0;
            // remap: u = wh*3+it enumerates 6 of the 12 (cg,ks2) units; second
            // set handled by second pass below. Simpler: unit = wh*6 + it*2
            // Use linear unit index:
            int unit = wh * 6 + it * 2;           // 0,2,4 / 6,8,10
#pragma unroll
            for (int dd = 0; dd < 2; dd++) {      // +0, +1
                int uu  = unit + dd;              // 0..11
                cg  = uu >> 1;
                ks2 = uu & 1;
                int cb = cg * 32 + ks2 * 16 + cbj;
                float2 v00 = {0.f, 0.f}, v01 = {0.f, 0.f};
                float2 v10 = {0.f, 0.f}, v11 = {0.f, 0.f};
                if (ok0) {
                    v00 = *(const float2*)&sr[sx0][cb];
                    v01 = *(const float2*)&sr[sx0][cb + 8];
                }
                if (ok1) {
                    v10 = *(const float2*)&sr[sx1][cb];
                    v11 = *(const float2*)&sr[sx1][cb + 8];
                }
                __half2 h0 = __floats2half2_rn(v00.x, v00.y);
                __half2 h1 = __floats2half2_rn(v10.x, v10.y);
                __half2 h2 = __floats2half2_rn(v01.x, v01.y);
                __half2 h3 = __floats2half2_rn(v11.x, v11.y);
                uint4 o;
                o.x = *(uint32_t*)&h0;  o.y = *(uint32_t*)&h1;
                o.z = *(uint32_t*)&h2;  o.w = *(uint32_t*)&h3;
                dst[(cg * 8 + ks2 * 4 + mi) * 32 + lane] = o;
            }
        }
    }
}

// ---------------------------------------------------------------------------
// Kernel T: transpose conv1_w (validated)
// ---------------------------------------------------------------------------
__global__ void kT(const float* __restrict__ k1) {
    int i = blockIdx.x * 256 + threadIdx.x;
    if (i >= TAPS * WNN * CC) return;
    int tap = i / (WNN * CC);
    int rc  = i - tap * (WNN * CC);
    g_k1T[i] = k1[(size_t)rc * TAPS + tap];
}

// ---------------------------------------------------------------------------
// Kernel A: pooled depthwise stats, 4-way row-split (validated R14)
// ---------------------------------------------------------------------------
__global__ void __launch_bounds__(768)
kA(const float* __restrict__ x, const float* __restrict__ k1,
   const float* __restrict__ dcw, const float* __restrict__ dcb) {
    int b   = blockIdx.x >> 4;
    int win = blockIdx.x & 15;
    int g   = threadIdx.x / 192;
    int c   = threadIdx.x % 192;
    int rb  = win >> 2, cb = win & 3;
    const float* xp = x + ((size_t)b * RR * RR) * CC + c;
    int base = (rb * WSZ) * RR + cb * WSZ;

    float Tp = 0.f, c0p = 0.f, c15p = 0.f;
    float r0 = 0.f, r15 = 0.f, e00 = 0.f, e0f = 0.f, ef0 = 0.f, eff = 0.f;
#pragma unroll
    for (int ii = 0; ii < 4; ii++) {
        int i = g * 4 + ii;
        float rowacc = 0.f, vj0 = 0.f, vj15 = 0.f;
#pragma unroll
        for (int j = 0; j < 16; j++) {
            float v = xp[(size_t)(base + i * RR + j) * CC];
            rowacc += v;
            if (j == 0)  { c0p  += v; vj0  = v; }
            if (j == 15) { c15p += v; vj15 = v; }
        }
        Tp += rowacc;
        if (i == 0)  { r0  = rowacc; e00 = vj0; e0f = vj15; }
        if (i == 15) { r15 = rowacc; ef0 = vj0; eff = vj15; }
    }

    __shared__ float sT[4][192], sc0[4][192], sc15[4][192];
    __shared__ float sr0[192], sr15[192], sE[4][192];
    __shared__ float red[192];
    sT[g][c] = Tp;  sc0[g][c] = c0p;  sc15[g][c] = c15p;
    if (g == 0) { sr0[c] = r0;  sE[0][c] = e00; sE[1][c] = e0f; }
    if (g == 3) { sr15[c] = r15; sE[2][c] = ef0; sE[3][c] = eff; }
    __syncthreads();

    if (g == 0) {
        float T   = sT[0][c] + sT[1][c] + sT[2][c] + sT[3][c];
        float c0  = sc0[0][c] + sc0[1][c] + sc0[2][c] + sc0[3][c];
        float c15 = sc15[0][c] + sc15[1][c] + sc15[2][c] + sc15[3][c];
        float Rex[3] = { sr15[c], 0.f, sr0[c] };
        float Cex[3] = { c15, 0.f, c0 };
        float e00v = sE[0][c], e0fv = sE[1][c], ef0v = sE[2][c], effv = sE[3][c];
        const float* kp = k1 + (size_t)(win * CC + c) * TAPS;
        float pooled = 0.f;
#pragma unroll
        for (int p = 0; p < 3; p++) {
#pragma unroll
            for (int q = 0; q < 3; q++) {
                float corner = 0.f;
                if (p == 0 && q == 0) corner = effv;
                if (p == 0 && q == 2) corner = ef0v;
                if (p == 2 && q == 0) corner = e0fv;
                if (p == 2 && q == 2) corner = e00v;
                float S = T - Rex[p] - Cex[q] + corner;
                pooled += kp[p * 3 + q] * S;
            }
        }
        pooled *= (1.f / 256.f);
        red[c] = pooled * dcw[win * CC + c];
    }
    __syncthreads();
    for (int s = 96; s >= 6; s >>= 1) {
        if (g == 0 && c < s) red[c] += red[c + s];
        __syncthreads();
    }
    if (threadIdx.x == 0) {
        float tot = red[0] + red[1] + red[2] + red[3] + red[4] + red[5];
        g_t[b * WNN + win] = tot + dcb[win];
    }
}

// ---------------------------------------------------------------------------
// Kernel W: fused MLP + Weff in fp16 B-fragment order (validated R13)
// ---------------------------------------------------------------------------
__global__ void __launch_bounds__(192)
kW(const float* __restrict__ gkb, const float* __restrict__ fw,
   const float* __restrict__ l1w, const float* __restrict__ l1b,
   const float* __restrict__ l2w, const float* __restrict__ l2b,
   const float* __restrict__ gkw) {
    int n = blockIdx.x;          // cout
    int c = threadIdx.x;         // cin = k
    __shared__ float ts[64], hs[256];
    __shared__ float sw_[64], swg[64];

    if (c < 64) ts[c] = g_t[c];
    __syncthreads();
    for (int u = c; u < 256; u += 192) {
        int b = u >> 6, j = u & 63;
        float a = l1b[j];
#pragma unroll
        for (int s = 0; s < 16; s++) a += ts[b * 16 + s] * l1w[j * 16 + s];
        hs[u] = 0.5f * a * (1.f + erff(a * 0.70710678118654752f));
    }
    __syncthreads();
    if (c < 64) {
        int b = c >> 4, s = c & 15;
        float a = l2b[s];
#pragma unroll
        for (int j = 0; j < 64; j++) a += hs[b * 64 + j] * l2w[s * 64 + j];
        float wv = 1.f / (1.f + expf(-a));
        sw_[c] = wv;
        swg[c] = wv * gkw[s];
    }
    __syncthreads();

    float f[17];
    const float* fp = fw + (size_t)n * ((WNN + 1) * CC) + c;
#pragma unroll
    for (int s = 0; s < 17; s++) f[s] = fp[s * CC];
    float g0 = gkb[0];

    int cg  = c >> 5, k32 = c & 31;
    int ks2 = k32 >> 4, kk = k32 & 15;
    int n8  = n >> 3;
    int lane = (n & 7) * 4 + ((kk & 7) >> 1);
    int reg  = ks2 * 2 + (kk >> 3);
    int hidx = kk & 1;
    int wrd  = ((n8 * 32 + lane) * 4 + reg) * 2 + hidx;

#pragma unroll 1
    for (int tap = 0; tap < 9; tap++) {
        float kv[16];
        const float* kt = g_k1T + (size_t)tap * WNN * CC + c;
#pragma unroll
        for (int s = 0; s < 16; s++) kv[s] = kt[s * CC];
#pragma unroll
        for (int b = 0; b < 4; b++) {
            float acc = 0.f, ga = g0;
#pragma unroll
            for (int s = 0; s < 16; s++) {
                acc = fmaf(sw_[b * 16 + s] * kv[s], f[s], acc);
                ga  = fmaf(swg[b * 16 + s], kv[s], ga);
            }
            acc = fmaf(ga, f[16], acc);
            g_WBh[((size_t)(b * 9 + tap) * 6 + cg) * 6144 + wrd] =
                __float2half_rn(acc);
        }
    }
}

// ---------------------------------------------------------------------------
// Kernel D: fp16 m16n8k16 implicit GEMM, N-split (validated R14/R15).
// CTA: M=64 x N=96, 4 warps of 64m x 24n. Grid 512, occupancy 4.
// ---------------------------------------------------------------------------
__global__ void __launch_bounds__(128, 4)
kD(const float* __restrict__ fb, float* __restrict__ out) {
    int tid  = threadIdx.x;
    int lane = tid & 31;
    int wid  = tid >> 5;
    int row  = blockIdx.x;             // image row
    int nq   = blockIdx.y;             // n half (0/1)
    int b    = blockIdx.z;

    const uint4* WBu = (const uint4*)g_WBh + (size_t)b * TAPS * 6 * 768;
    int n8base = nq * 12 + wid * 3;

    float acc[4][3][4];
#pragma unroll
    for (int mi = 0; mi < 4; mi++)
#pragma unroll
        for (int ni = 0; ni < 3; ni++)
#pragma unroll
            for (int r = 0; r < 4; r++) acc[mi][ni][r] = 0.f;

    uint4 bfA[3], bfB[3];

    auto loadB = [&](int kc, uint4 (&bf)[3]) {
        int tap = kc / 6, cg = kc - tap * 6;
        const uint4* src = WBu + (tap * 6 + cg) * 768 + n8base * 32 + lane;
#pragma unroll
        for (int ni = 0; ni < 3; ni++) bf[ni] = src[ni * 32];
    };
    auto prefA = [&](int kc) {
        if (kc >= 54) return;
        int tap = kc / 6, cg = kc - tap * 6;
        int dy = tap / 3 - 1, dxi = tap % 3;
        int sy = row + dy;
        if ((unsigned)sy >= RR) return;
        const char* p = (const char*)(g_xAh +
            ((size_t)(b * 3 + dxi) * RR + sy) * 1536 + cg * 8 * 32);
        asm volatile("prefetch.global.L1 [%0];" :: "l"(p + lane * 128));
    };
    auto computeChunk = [&](int kc, uint4 (&bf)[3]) {
        int tap = kc / 6, cg = kc - tap * 6;
        int dy = tap / 3 - 1, dxi = tap % 3;
        int sy = row + dy;
        if ((unsigned)sy >= RR) return;          // zero A -> no contribution
        const uint4* ab = g_xAh +
            ((size_t)(b * 3 + dxi) * RR + sy) * 1536 + cg * 8 * 32;
        uint4 av[8];
#pragma unroll
        for (int q = 0; q < 8; q++) av[q] = ab[q * 32 + lane];   // 8 LDG in flight
#pragma unroll
        for (int ks2 = 0; ks2 < 2; ks2++) {
#pragma unroll
            for (int mi = 0; mi < 4; mi++) {
                uint32_t af[4];
                uint4 v = av[ks2 * 4 + mi];
                af[0] = v.x; af[1] = v.y; af[2] = v.z; af[3] = v.w;
#pragma unroll
                for (int ni = 0; ni < 3; ni++) {
                    uint32_t bb[2];
                    bb[0] = ks2 ? bf[ni].z : bf[ni].x;
                    bb[1] = ks2 ? bf[ni].w : bf[ni].y;
                    mma_f16(acc[mi][ni], af, bb);
                }
            }
        }
    };

    loadB(0, bfA);
#pragma unroll 1
    for (int it = 0; it < 27; it++) {
        int kc = it * 2;
        loadB(kc + 1, bfB);
        if (wid == 0) prefA(kc + 1);
        computeChunk(kc, bfA);
        if (kc + 2 < 54) loadB(kc + 2, bfA);
        if (wid == 0) prefA(kc + 2);
        computeChunk(kc + 1, bfB);
    }

    // ---- epilogue: +bias, STG.64 ----
#pragma unroll
    for (int ni = 0; ni < 3; ni++) {
        int co = nq * 96 + wid * 24 + ni * 8 + (lane & 3) * 2;
        float bx = fb[co], by = fb[co + 1];
#pragma unroll
        for (int mi = 0; mi < 4; mi++) {
            int m0 = row * 64 + mi * 16 + (lane >> 2);
            size_t o0 = ((size_t)b * RR * RR + m0) * CC + co;
            *(float2*)(out + o0) =
                make_float2(acc[mi][ni][0] + bx, acc[mi][ni][1] + by);
            *(float2*)(out + o0 + (size_t)8 * CC) =
                make_float2(acc[mi][ni][2] + bx, acc[mi][ni][3] + by);
        }
    }
}

// ---------------------------------------------------------------------------
extern "C" void kernel_launch(void* const* d_in, const int* in_sizes, int n_in,
                              void* d_out, int out_size) {
    const float* x   = (const float*)d_in[0];
    const float* k1  = (const float*)d_in[1];
    const float* dcw = (const float*)d_in[2];
    const float* dcb = (const float*)d_in[3];
    const float* l1w = (const float*)d_in[4];
    const float* l1b = (const float*)d_in[5];
    const float* l2w = (const float*)d_in[6];
    const float* l2b = (const float*)d_in[7];
    const float* gkw = (const float*)d_in[8];
    const float* gkb = (const float*)d_in[9];
    const float* fw  = (const float*)d_in[10];
    const float* fb  = (const float*)d_in[11];
    float* out = (float*)d_out;

    static cudaStream_t s1 = nullptr;
    static cudaEvent_t evF = nullptr, evJ = nullptr;
    if (s1 == nullptr) {
        cudaStreamCreateWithFlags(&s1, cudaStreamNonBlocking);
        cudaEventCreateWithFlags(&evF, cudaEventDisableTiming);
        cudaEventCreateWithFlags(&evJ, cudaEventDisableTiming);
    }

    // fork: side chain (kT -> kA -> kW) runs concurrently with kX
    cudaEventRecord(evF, 0);
    cudaStreamWaitEvent(s1, evF, 0);

    kT<<<(TAPS * WNN * CC + 255) / 256, 256, 0, s1>>>(k1);
    kA<<<BB * WNN, 768, 0, s1>>>(x, k1, dcw, dcb);
    kW<<<CC, CC, 0, s1>>>(gkb, fw, l1w, l1b, l2w, l2b, gkw);
    cudaEventRecord(evJ, s1);

    kX<<<BB * RR, 256>>>(x);

    // join
    cudaStreamWaitEvent(0, evJ, 0);
    dim3 g(RR, 2, BB);   // 64 rows x 2 n-halves x 4 batches = 512 CTAs
    kD<<<g, 256 / 2>>>(fb, out);
}